// round 12
// baseline (speedup 1.0000x reference)
#include <cuda_runtime.h>
#include <cstdint>
#include <math.h>

#define HID   128
#define G4    512
#define OUTC  7
#define LEN   2048
#define BATCH 10
#define CL    4     // cluster size
#define TPB   160   // 4 matvec warps (128 gate rows) + 1 control warp

// Packed fp32x2 FMA (Blackwell): 2 fp32 FMAs per lane per issue.
#define FMA2(d,a,b,c) asm("fma.rn.f32x2 %0, %1, %2, %3;" : "=l"(d) : "l"(a), "l"(b), "l"(c))

__device__ __forceinline__ unsigned smem_u32(const void* p) {
    return (unsigned)__cvta_generic_to_shared(p);
}
__device__ __forceinline__ unsigned my_ctarank() {
    unsigned r; asm("mov.u32 %0, %%cluster_ctarank;" : "=r"(r)); return r;
}
__device__ __forceinline__ unsigned mapa_u32(unsigned a, unsigned r) {
    unsigned o; asm("mapa.shared::cluster.u32 %0, %1, %2;" : "=r"(o) : "r"(a), "r"(r)); return o;
}
#define CLUSTER_SYNC() do { \
    asm volatile("barrier.cluster.arrive.aligned;" ::: "memory"); \
    asm volatile("barrier.cluster.wait.aligned;"   ::: "memory"); \
} while (0)

#define MBAR_WAIT_CL(addr, parity) do {                                          \
    unsigned _done;                                                              \
    do {                                                                         \
        asm volatile("{\n\t.reg .pred p;\n\t"                                    \
            "mbarrier.try_wait.parity.acquire.cluster.shared::cta.b64 p, [%1], %2, 0x989680;\n\t" \
            "selp.b32 %0, 1, 0, p;\n\t}"                                         \
            : "=r"(_done) : "r"(addr), "r"(parity) : "memory");                  \
    } while (!_done);                                                            \
} while (0)

// HW tanh (MUFU.TANH, sm_75+): ~16 cyc, rel err ~1e-5 (budget 1e-3).
__device__ __forceinline__ float htanh(float x) {
    float y; asm("tanh.approx.f32 %0, %1;" : "=f"(y) : "f"(x)); return y;
}
__device__ __forceinline__ float hsig(float x) {
    return fmaf(0.5f, htanh(0.5f * x), 0.5f);
}

// 4-CTA cluster per batch element (grid = 40). CTA r owns the 128 gate rows of
// units [32r, 32r+32) (all four gates). mv warp w owns all 4 gates of units
// 8w..8w+7 (lane = qg*8+ui) -> cell via 3 intra-warp shuffles; c in registers.
// Per step: full-h dot from 64 packed-f32x2 weight regs (issue floor 128
// cyc/SMSP at 4 CTAs), 32 h2 values multicast to 3 peers via DSMEM stores +
// release-arrives on ping-pong mbarriers (count 96). Control warp overlaps
// step t-1 logits/argmax with step t's dot and publishes sidx BEFORE softmax.
__global__ void __cluster_dims__(CL,1,1) __launch_bounds__(TPB, 1)
lstm_decode_kernel(const float* __restrict__ h0,      const float* __restrict__ c0,
                   const float* __restrict__ tgt_oh,  const unsigned* __restrict__ tf_mask,
                   const float* __restrict__ W_ih,    const float* __restrict__ W_hh,
                   const float* __restrict__ b_ih,    const float* __restrict__ b_hh,
                   const float* __restrict__ W_out,   const float* __restrict__ b_out,
                   float* __restrict__ out)
{
    __shared__ __align__(16) float h_sm[3][HID];     // triple-buffered h (global unit idx)
    __shared__ float wih_t[OUTC * G4];               // W_ih transposed [c][row]
    __shared__ float wout_sm[OUTC * HID];
    __shared__ float bout_sm[OUTC];
    __shared__ __align__(8) unsigned long long mbar[2];  // ping-pong, count=96
    __shared__ unsigned sidx_word;                   // (tag<<3)|sidx
    __shared__ short tfidx_sm[LEN];

    const int      tid  = threadIdx.x;
    const unsigned rank = my_ctarank();
    const int      b    = blockIdx.x / CL;
    const bool     mv   = tid < 128;
    const int      wi   = tid >> 5;                  // warp 0..4
    const int      l    = tid & 31;
    const int      ui   = l & 7;                     // unit-in-warp
    const int      qg   = l >> 3;                    // gate 0..3 (i,f,g,o)
    const int      uu   = (int)rank * 32 + wi * 8 + ui;  // owned unit (mv only)
    const int      row  = qg * HID + uu;             // owned gate row

    // --- one-time setup -----------------------------------------------------
    unsigned long long w[64];                        // 128 weights packed f32x2
    float bias = 0.0f, c = 0.0f;
    float wout_reg[28];                              // control warp: W_out by lane
    if (mv) {
        const unsigned long long* wr = (const unsigned long long*)(W_hh + (size_t)row * HID);
        #pragma unroll
        for (int k = 0; k < 64; k++) w[k] = wr[k];
        bias = b_ih[row] + b_hh[row];
        if (l < 8) c = c0[b * HID + uu];             // c kept in register
    }
    for (int i = tid; i < OUTC * G4; i += TPB) {     // transpose W_ih
        int cc = i >> 9, r0 = i & 511;
        wih_t[i] = W_ih[r0 * OUTC + cc];
    }
    for (int i = tid; i < OUTC * HID; i += TPB) wout_sm[i] = W_out[i];
    if (tid < OUTC) bout_sm[tid] = b_out[tid];
    if (tid < HID) h_sm[0][tid] = h0[b * HID + tid];
    if (tid == 0) {
        sidx_word = (unsigned)(OUTC - 1);            // tag 0, x0 = one-hot OUT-1
        asm volatile("mbarrier.init.shared.b64 [%0], %1;" :: "r"(smem_u32(&mbar[0])), "r"(96u) : "memory");
        asm volatile("mbarrier.init.shared.b64 [%0], %1;" :: "r"(smem_u32(&mbar[1])), "r"(96u) : "memory");
    }
    for (int t = tid; t < LEN; t += TPB) {           // teacher-forcing indices
        short v = -1;
        if (tf_mask[t] != 0u) {
            v = 0;
            #pragma unroll
            for (int k = 0; k < OUTC; k++)
                if (tgt_oh[(t + 1) * OUTC + k] > 0.5f) v = (short)k;
        }
        tfidx_sm[t] = v;
    }
    __syncthreads();
    if (!mv) {                                       // control: W_out into regs
        #pragma unroll
        for (int k = 0; k < OUTC; k++)
            #pragma unroll
            for (int q = 0; q < 4; q++)
                wout_reg[k * 4 + q] = wout_sm[k * HID + l + 32 * q];
    }
    CLUSTER_SYNC();   // smem/mbar init visible cluster-wide before any remote op

    const unsigned mb_l0 = smem_u32(&mbar[0]);
    unsigned mb_rp[3], h_rp[3];                      // 3 peers
    {
        const unsigned h_l0 = smem_u32(&h_sm[0][0]);
        int j = 0;
        #pragma unroll
        for (unsigned r = 0; r < CL; r++) {
            if (r == rank) continue;
            mb_rp[j] = mapa_u32(mb_l0, r);
            h_rp[j]  = mapa_u32(h_l0, r);
            j++;
        }
    }
    volatile unsigned* sw = &sidx_word;

    int cur3 = 0, nxt3 = 1;                          // read cur3, write nxt3

    // --- time loop: iteration t = matvec/cell of step t + control of t-1 ----
    for (int t = 0; t <= LEN; t++) {
        // wait for all peers' step t-1 h exchange (96 release-arrives)
        if (t > 0) {
            MBAR_WAIT_CL(mb_l0 + (((t - 1) & 1) << 3), ((t - 1) >> 1) & 1);
        }
        const float* hb = h_sm[cur3];

        float p = 0.0f;
        if (mv && t < LEN) {
            // full-h dot: 4 segments, 4 independent FMA2 chains
            unsigned long long acc[4] = {0ull, 0ull, 0ull, 0ull};
            #pragma unroll
            for (int s = 0; s < 4; s++) {
                #pragma unroll
                for (int q = 0; q < 8; q++) {
                    ulonglong2 hv = *reinterpret_cast<const ulonglong2*>(hb + 32 * s + 4 * q);
                    FMA2(acc[s], w[16 * s + 2 * q],     hv.x, acc[s]);
                    FMA2(acc[s], w[16 * s + 2 * q + 1], hv.y, acc[s]);
                }
            }
            float2 f0 = *reinterpret_cast<float2*>(&acc[0]);
            float2 f1 = *reinterpret_cast<float2*>(&acc[1]);
            float2 f2 = *reinterpret_cast<float2*>(&acc[2]);
            float2 f3 = *reinterpret_cast<float2*>(&acc[3]);
            p = ((f0.x + f0.y) + (f1.x + f1.y)) + ((f2.x + f2.y) + (f3.x + f3.y));
        }
        if (!mv && t > 0) {                          // control warp: step t-1
            float hj[4];
            #pragma unroll
            for (int q = 0; q < 4; q++) hj[q] = hb[l + 32 * q];
            float pk[OUTC];
            #pragma unroll
            for (int k = 0; k < OUTC; k++) {
                float s = 0.0f;
                #pragma unroll
                for (int q = 0; q < 4; q++) s = fmaf(hj[q], wout_reg[k * 4 + q], s);
                #pragma unroll
                for (int off = 16; off; off >>= 1)
                    s += __shfl_xor_sync(0xffffffffu, s, off);   // all lanes get sum
                pk[k] = s;
            }
            float lv = -3.4e38f;
            if (l < OUTC) {
                float v = pk[0];
                if (l == 1) v = pk[1];
                if (l == 2) v = pk[2];
                if (l == 3) v = pk[3];
                if (l == 4) v = pk[4];
                if (l == 5) v = pk[5];
                if (l == 6) v = pk[6];
                lv = v + bout_sm[l];
            }
            float m = lv; int ai = (l < OUTC) ? l : 1000;
            #pragma unroll
            for (int off = 16; off; off >>= 1) {
                float om = __shfl_xor_sync(0xffffffffu, m, off);
                int   oi = __shfl_xor_sync(0xffffffffu, ai, off);
                if (om > m || (om == m && oi < ai)) { m = om; ai = oi; }
            }
            if (l == 0) {                            // publish sidx EARLY (pre-softmax)
                int tv = tfidx_sm[t - 1];
                int si = (tv >= 0) ? tv : ai;
                *sw = ((unsigned)t << 3) | (unsigned)si;
            }
            float e = (l < OUTC) ? __expf(lv - m) : 0.0f;
            float s2 = e;
            #pragma unroll
            for (int off = 16; off; off >>= 1) s2 += __shfl_xor_sync(0xffffffffu, s2, off);
            if (l < OUTC && rank == 0) {
                float lg = __logf(s2);
                out[((size_t)b * LEN + (t - 1)) * OUTC + l] = lv - m - lg;
            }
        }

        // gate + activation (MUFU.TANH) + in-warp cell + 3-peer exchange
        if (mv && t < LEN) {
            unsigned v;                              // spin for sidx tag == t
            do { v = *sw; } while ((v >> 3) != (unsigned)t);
            float gv = p + bias + wih_t[(v & 7u) * G4 + row];    // x is one-hot
            float a  = (qg == 2) ? htanh(gv) : hsig(gv);
            float aF = __shfl_sync(0xffffffffu, a, ui + 8);
            float aG = __shfl_sync(0xffffffffu, a, ui + 16);
            float aO = __shfl_sync(0xffffffffu, a, ui + 24);
            if (l < 8) {                             // lane owns unit uu
                float c2 = aF * c + a * aG;          // a == aI here
                float h2 = aO * htanh(c2);
                c = c2;
                h_sm[nxt3][uu] = h2;
                const unsigned off = (unsigned)((nxt3 * HID + uu) * 4);
                #pragma unroll
                for (int j = 0; j < 3; j++)
                    asm volatile("st.shared::cluster.f32 [%0], %1;"
                                 :: "r"(h_rp[j] + off), "f"(h2) : "memory");
                #pragma unroll
                for (int j = 0; j < 3; j++)          // release orders prior stores
                    asm volatile("mbarrier.arrive.release.cluster.shared::cluster.b64 _, [%0];"
                                 :: "r"(mb_rp[j] + ((t & 1) << 3)) : "memory");
            }
        }
        __syncthreads();   // one bar/step

        cur3 = nxt3; nxt3 = (nxt3 == 2) ? 0 : nxt3 + 1;
    }

    // final states: h produced at t=LEN-1 lives in buffer LEN%3; c in regs
    if (mv && l < 8) {
        out[(size_t)BATCH * LEN * OUTC + b * HID + uu]               = h_sm[LEN % 3][uu];
        out[(size_t)BATCH * LEN * OUTC + BATCH * HID + b * HID + uu] = c;
    }
    CLUSTER_SYNC();   // keep smem alive until peers' last remote ops land
}

extern "C" void kernel_launch(void* const* d_in, const int* in_sizes, int n_in,
                              void* d_out, int out_size)
{
    (void)in_sizes; (void)n_in; (void)out_size;
    lstm_decode_kernel<<<BATCH * CL, TPB>>>(
        (const float*)d_in[0], (const float*)d_in[1], (const float*)d_in[2],
        (const unsigned*)d_in[3], (const float*)d_in[4], (const float*)d_in[5],
        (const float*)d_in[6], (const float*)d_in[7], (const float*)d_in[8],
        (const float*)d_in[9], (float*)d_out);
}